// round 9
// baseline (speedup 1.0000x reference)
#include <cuda_runtime.h>
#include <cuda_fp16.h>

#define N_NODES 50000
#define F 64
#define HDIM 128          // h1 (64) and h2 (64) interleaved per node, fp16
#define BSTRIDE 128       // bucket region per node (4 reps x 32 cap)
#define BCAP 32
#define NREP 4

// Scratch: __device__ globals (allocation-free, graph-capturable).
// Invariant: g_cursor is all-zero at kernel_launch entry (zero at module load;
// agg_kernel re-zeroes after reading, every run).
__device__ __align__(16) __half g_h[(size_t)N_NODES * HDIM];     // [N][128] fp16
__device__ float g_dinv[N_NODES];
__device__ float g_invdeg[N_NODES];
__device__ __align__(16) int g_cursor[NREP * N_NODES];           // per (node, rep)
__device__ int g_srcsorted[(size_t)N_NODES * BSTRIDE];           // bucketed src ids

// ---------------------------------------------------------------------------
// Scatter src ids into fixed-stride dst buckets, 4 cursor replicas per node.
// 4 edges per thread via int4. Dedicated kernel: small footprint, high occ.
// ---------------------------------------------------------------------------
__global__ void __launch_bounds__(256) scatter_kernel(const int* __restrict__ ei, int E) {
    int t = blockIdx.x * 256 + threadIdx.x;
    int rep = t & (NREP - 1);
    int base = t * 4;
    if (base + 4 <= E) {
        int4 s = *(const int4*)(ei + base);
        int4 d = *(const int4*)(ei + E + base);
        int p0 = atomicAdd(&g_cursor[d.x * NREP + rep], 1);
        int p1 = atomicAdd(&g_cursor[d.y * NREP + rep], 1);
        int p2 = atomicAdd(&g_cursor[d.z * NREP + rep], 1);
        int p3 = atomicAdd(&g_cursor[d.w * NREP + rep], 1);
        g_srcsorted[(size_t)d.x * BSTRIDE + rep * BCAP + p0] = s.x;
        g_srcsorted[(size_t)d.y * BSTRIDE + rep * BCAP + p1] = s.y;
        g_srcsorted[(size_t)d.z * BSTRIDE + rep * BCAP + p2] = s.z;
        g_srcsorted[(size_t)d.w * BSTRIDE + rep * BCAP + p3] = s.w;
    } else {
        for (int e = base; e < E; e++) {
            int d = ei[E + e];
            int pos = atomicAdd(&g_cursor[d * NREP + rep], 1);
            g_srcsorted[(size_t)d * BSTRIDE + rep * BCAP + pos] = ei[e];
        }
    }
}

// ---------------------------------------------------------------------------
// GEMM + dinv, block-partitioned. Blocks [0, nGemm): HMMA dual-GEMM with
// in-kernel f32->fp16 conversion of x and W. Blocks [nGemm, ...): per-node
// degree -> dinv/invdeg (trivial, tolerates the gemm resource envelope).
// ---------------------------------------------------------------------------
__global__ void __launch_bounds__(256) gemm_dinv_kernel(
    const float* __restrict__ x,
    const float* __restrict__ W1,
    const float* __restrict__ W2,
    int nGemm) {

    __shared__ __half xs[128][72];
    __shared__ __half ws[128][72];

    int tid = threadIdx.x;

    if ((int)blockIdx.x >= nGemm) {
        // ----------------- dinv partition -----------------
        int i = (blockIdx.x - nGemm) * 256 + tid;
        if (i < N_NODES) {
            int4 c = *(const int4*)(g_cursor + i * NREP);
            float dg = (float)(c.x + c.y + c.z + c.w + 1);  // +1 self loop
            g_invdeg[i] = 1.0f / dg;
            g_dinv[i]   = rsqrtf(dg);
        }
        return;
    }

    // ----------------- gemm partition -----------------
    int row0 = blockIdx.x * 128;

    // Load x tile (f32 -> fp16 into smem), coalesced float4 reads.
    for (int i = tid; i < 128 * 16; i += 256) {
        int r = i >> 4, c4 = i & 15;
        int row = row0 + r;
        float4 v = make_float4(0.f, 0.f, 0.f, 0.f);
        if (row < N_NODES) v = *(const float4*)(x + (size_t)row * F + c4 * 4);
        __half2 h0 = __floats2half2_rn(v.x, v.y);
        __half2 h1 = __floats2half2_rn(v.z, v.w);
        uint2 o = make_uint2(*reinterpret_cast<unsigned*>(&h0),
                             *reinterpret_cast<unsigned*>(&h1));
        *(uint2*)&xs[r][c4 * 4] = o;
    }
    // Load W (f32, coalesced) -> ws[c][k] fp16 (n-major, transposed in smem).
    for (int i = tid; i < 128 * 64; i += 256) {
        int k = i >> 7, c = i & 127;
        float v = (c < 64) ? W1[k * 64 + c] : W2[k * 64 + (c - 64)];
        ws[c][k] = __float2half_rn(v);
    }
    __syncthreads();

    int warp = tid >> 5, lane = tid & 31;
    int g = lane >> 2, t = lane & 3;
    int wrow = warp * 16;

    float c[16][4];
    #pragma unroll
    for (int nt = 0; nt < 16; nt++)
        #pragma unroll
        for (int j = 0; j < 4; j++) c[nt][j] = 0.0f;

    #pragma unroll
    for (int ks = 0; ks < 4; ks++) {
        int kb = ks * 16;
        unsigned a0 = *(const unsigned*)&xs[wrow + g][kb + 2 * t];
        unsigned a1 = *(const unsigned*)&xs[wrow + g + 8][kb + 2 * t];
        unsigned a2 = *(const unsigned*)&xs[wrow + g][kb + 2 * t + 8];
        unsigned a3 = *(const unsigned*)&xs[wrow + g + 8][kb + 2 * t + 8];
        #pragma unroll
        for (int nt = 0; nt < 16; nt++) {
            unsigned b0 = *(const unsigned*)&ws[nt * 8 + g][kb + 2 * t];
            unsigned b1 = *(const unsigned*)&ws[nt * 8 + g][kb + 2 * t + 8];
            asm volatile(
                "mma.sync.aligned.m16n8k16.row.col.f32.f16.f16.f32 "
                "{%0,%1,%2,%3}, {%4,%5,%6,%7}, {%8,%9}, {%0,%1,%2,%3};"
                : "+f"(c[nt][0]), "+f"(c[nt][1]), "+f"(c[nt][2]), "+f"(c[nt][3])
                : "r"(a0), "r"(a1), "r"(a2), "r"(a3), "r"(b0), "r"(b1));
        }
    }

    int r1 = row0 + wrow + g;
    int r2 = r1 + 8;
    #pragma unroll
    for (int nt = 0; nt < 16; nt++) {
        int col = nt * 8 + 2 * t;
        if (r1 < N_NODES) {
            __half2 h = __floats2half2_rn(c[nt][0], c[nt][1]);
            *(__half2*)(g_h + (size_t)r1 * HDIM + col) = h;
        }
        if (r2 < N_NODES) {
            __half2 h = __floats2half2_rn(c[nt][2], c[nt][3]);
            *(__half2*)(g_h + (size_t)r2 * HDIM + col) = h;
        }
    }
}

// ---------------------------------------------------------------------------
// Aggregation: one warp per destination node. Lane l owns cols 4l..4l+3.
// 4 bucket segments (<=32 each); lanes pre-load src+norm (padded lanes get
// nrm=0, src=node), then fixed-8-unrolled broadcast subchunks.
// Re-zeroes this node's cursors at the end (restores the entry invariant).
// ---------------------------------------------------------------------------
__global__ void __launch_bounds__(256) agg_kernel(float* __restrict__ out) {
    int node = (blockIdx.x * blockDim.x + threadIdx.x) >> 5;
    int lane = threadIdx.x & 31;
    if (node >= N_NODES) return;

    float di = g_dinv[node];
    int4 cc = *(const int4*)(g_cursor + node * NREP);
    if (lane == 0)
        *(int4*)(g_cursor + node * NREP) = make_int4(0, 0, 0, 0);
    int cnt_arr[4] = {cc.x, cc.y, cc.z, cc.w};

    // self-loop term: di*di * h[node]
    float ax, ay, az, aw;
    {
        uint2 v = *((const uint2*)(g_h + (size_t)node * HDIM) + lane);
        float2 f0 = __half22float2(*reinterpret_cast<__half2*>(&v.x));
        float2 f1 = __half22float2(*reinterpret_cast<__half2*>(&v.y));
        float self = di * di;
        ax = self * f0.x; ay = self * f0.y; az = self * f1.x; aw = self * f1.y;
    }

    #pragma unroll
    for (int rep = 0; rep < NREP; rep++) {
        int cnt = cnt_arr[rep];
        const int* src = g_srcsorted + (size_t)node * BSTRIDE + rep * BCAP;

        int   sv = node; float nv = 0.0f;
        if (lane < cnt) { sv = src[lane]; nv = di * g_dinv[sv]; }

        int nsub = (cnt + 7) >> 3;
        for (int sub = 0; sub < nsub; sub++) {
            int off = sub * 8;
            #pragma unroll
            for (int u = 0; u < 8; u++) {
                int   ss = __shfl_sync(0xffffffffu, sv, off + u);
                float nn = __shfl_sync(0xffffffffu, nv, off + u);
                uint2 v = *((const uint2*)(g_h + (size_t)ss * HDIM) + lane);
                float2 f0 = __half22float2(*reinterpret_cast<__half2*>(&v.x));
                float2 f1 = __half22float2(*reinterpret_cast<__half2*>(&v.y));
                ax = fmaf(nn, f0.x, ax);
                ay = fmaf(nn, f0.y, ay);
                az = fmaf(nn, f1.x, az);
                aw = fmaf(nn, f1.y, aw);
            }
        }
    }

    float inv = g_invdeg[node];
    ax *= inv; ay *= inv; az *= inv; aw *= inv;

    // lanes 0-15 hold layer1 (cols 0..63), lanes 16-31 hold layer2 (cols 64..127)
    int peer = (lane < 16) ? lane + 16 : lane;
    float bx = __shfl_sync(0xffffffffu, ax, peer);
    float by = __shfl_sync(0xffffffffu, ay, peer);
    float bz = __shfl_sync(0xffffffffu, az, peer);
    float bw = __shfl_sync(0xffffffffu, aw, peer);

    if (lane < 16) {
        float4 o;
        o.x = fmaxf(ax, 0.0f) * (1.0f / (1.0f + expf(-bx)));
        o.y = fmaxf(ay, 0.0f) * (1.0f / (1.0f + expf(-by)));
        o.z = fmaxf(az, 0.0f) * (1.0f / (1.0f + expf(-bz)));
        o.w = fmaxf(aw, 0.0f) * (1.0f / (1.0f + expf(-bw)));
        *((float4*)(out + (size_t)node * F) + lane) = o;
    }
}

// ---------------------------------------------------------------------------
extern "C" void kernel_launch(void* const* d_in, const int* in_sizes, int n_in,
                              void* d_out, int out_size) {
    const float* x  = (const float*)d_in[0];
    const int*   ei = (const int*)d_in[1];   // int32 (JAX x64 disabled)
    const float* W1 = (const float*)d_in[2];
    const float* W2 = (const float*)d_in[3];
    float* out = (float*)d_out;

    int E  = in_sizes[1] / 2;
    int T4 = (E + 3) / 4;
    int S  = (T4 + 255) / 256;               // scatter blocks
    int G  = (N_NODES + 127) / 128;          // gemm blocks
    int D  = (N_NODES + 255) / 256;          // dinv blocks

    scatter_kernel<<<S, 256>>>(ei, E);
    gemm_dinv_kernel<<<G + D, 256>>>(x, W1, W2, G);
    agg_kernel<<<(N_NODES * 32 + 255) / 256, 256>>>(out);  // one warp per node
}

// round 10
// speedup vs baseline: 1.3918x; 1.3918x over previous
#include <cuda_runtime.h>
#include <cuda_fp16.h>

#define N_NODES 50000
#define F 64
#define HDIM 128          // output cols of the dual GEMM (64 + 64)
#define BSTRIDE 128       // bucket region per node (4 reps x 32 cap)
#define BCAP 32
#define NREP 4

// Scratch: __device__ globals (allocation-free, graph-capturable).
__device__ __align__(16) __half g_xh[(size_t)N_NODES * F];   // x in fp16
__device__ __align__(16) __half g_a[(size_t)N_NODES * F];    // aggregated features fp16
__device__ __align__(16) __half g_wt[HDIM * F];              // Wt[c][k] fp16 (n-major)
__device__ float g_dinv[N_NODES];
__device__ float g_invdeg[N_NODES];
__device__ __align__(16) int g_cursor[NREP * N_NODES];       // per (node, rep)
__device__ int g_srcsorted[(size_t)N_NODES * BSTRIDE];       // bucketed src ids

// ---------------------------------------------------------------------------
// Prep: x -> fp16, W -> fp16 n-major, zero cursors. One light kernel.
// ---------------------------------------------------------------------------
__global__ void __launch_bounds__(256) prep_kernel(
    const float* __restrict__ x,
    const float* __restrict__ W1,
    const float* __restrict__ W2) {
    int i = blockIdx.x * 256 + threadIdx.x;

    if (i < N_NODES * F / 4) {
        float4 v = *(const float4*)(x + (size_t)i * 4);
        __half2 h0 = __floats2half2_rn(v.x, v.y);
        __half2 h1 = __floats2half2_rn(v.z, v.w);
        uint2 o = make_uint2(*reinterpret_cast<unsigned*>(&h0),
                             *reinterpret_cast<unsigned*>(&h1));
        *(uint2*)(g_xh + (size_t)i * 4) = o;
    }
    if (i < N_NODES) {
        *(int4*)(g_cursor + i * NREP) = make_int4(0, 0, 0, 0);
    }
    if (i < HDIM * F) {
        int c = i >> 6, k = i & 63;
        float v = (c < 64) ? W1[k * 64 + c] : W2[k * 64 + (c - 64)];
        g_wt[c * F + k] = __float2half_rn(v);
    }
}

// ---------------------------------------------------------------------------
// Scatter src ids into fixed-stride dst buckets, 4 cursor replicas per node.
// 4 edges per thread via int4. (Byte-identical to the measured R7 version.)
// ---------------------------------------------------------------------------
__global__ void __launch_bounds__(256) scatter_kernel(const int* __restrict__ ei, int E) {
    int t = blockIdx.x * 256 + threadIdx.x;
    int rep = t & (NREP - 1);
    int base = t * 4;
    if (base + 4 <= E) {
        int4 s = *(const int4*)(ei + base);
        int4 d = *(const int4*)(ei + E + base);
        int p0 = atomicAdd(&g_cursor[d.x * NREP + rep], 1);
        int p1 = atomicAdd(&g_cursor[d.y * NREP + rep], 1);
        int p2 = atomicAdd(&g_cursor[d.z * NREP + rep], 1);
        int p3 = atomicAdd(&g_cursor[d.w * NREP + rep], 1);
        g_srcsorted[(size_t)d.x * BSTRIDE + rep * BCAP + p0] = s.x;
        g_srcsorted[(size_t)d.y * BSTRIDE + rep * BCAP + p1] = s.y;
        g_srcsorted[(size_t)d.z * BSTRIDE + rep * BCAP + p2] = s.z;
        g_srcsorted[(size_t)d.w * BSTRIDE + rep * BCAP + p3] = s.w;
    } else {
        for (int e = base; e < E; e++) {
            int d = ei[E + e];
            int pos = atomicAdd(&g_cursor[d * NREP + rep], 1);
            g_srcsorted[(size_t)d * BSTRIDE + rep * BCAP + pos] = ei[e];
        }
    }
}

// ---------------------------------------------------------------------------
// deg = sum of 4 cursors + 1 (self loop) -> dinv, invdeg.
// ---------------------------------------------------------------------------
__global__ void __launch_bounds__(256) dinv_kernel() {
    int i = blockIdx.x * blockDim.x + threadIdx.x;
    if (i < N_NODES) {
        int4 c = *(const int4*)(g_cursor + i * NREP);
        float dg = (float)(c.x + c.y + c.z + c.w + 1);
        g_invdeg[i] = 1.0f / dg;
        g_dinv[i]   = rsqrtf(dg);
    }
}

// ---------------------------------------------------------------------------
// Aggregate x (NOT h): a[dst] = (sum norm * xh[src] + dinv^2 * xh[dst]) / deg.
// One warp per node; lane l owns cols 2l..2l+1 (one half2 = 4B -> warp reads
// one contiguous 128B line per edge). fp32 accumulation, fp16 store.
// ---------------------------------------------------------------------------
__global__ void __launch_bounds__(256) aggx_kernel() {
    int node = (blockIdx.x * blockDim.x + threadIdx.x) >> 5;
    int lane = threadIdx.x & 31;
    if (node >= N_NODES) return;

    float di = g_dinv[node];
    int4 cc = *(const int4*)(g_cursor + node * NREP);
    int cnt_arr[4] = {cc.x, cc.y, cc.z, cc.w};

    // self-loop term
    float ax, ay;
    {
        unsigned u = *(const unsigned*)(g_xh + (size_t)node * F + 2 * lane);
        float2 f = __half22float2(*reinterpret_cast<__half2*>(&u));
        float self = di * di;
        ax = self * f.x; ay = self * f.y;
    }

    #pragma unroll
    for (int rep = 0; rep < NREP; rep++) {
        int cnt = cnt_arr[rep];
        const int* src = g_srcsorted + (size_t)node * BSTRIDE + rep * BCAP;

        int   sv = node; float nv = 0.0f;
        if (lane < cnt) { sv = src[lane]; nv = di * g_dinv[sv]; }

        int nsub = (cnt + 7) >> 3;
        for (int sub = 0; sub < nsub; sub++) {
            int off = sub * 8;
            #pragma unroll
            for (int u = 0; u < 8; u++) {
                int   ss = __shfl_sync(0xffffffffu, sv, off + u);
                float nn = __shfl_sync(0xffffffffu, nv, off + u);
                unsigned v = *(const unsigned*)(g_xh + (size_t)ss * F + 2 * lane);
                float2 f = __half22float2(*reinterpret_cast<__half2*>(&v));
                ax = fmaf(nn, f.x, ax);
                ay = fmaf(nn, f.y, ay);
            }
        }
    }

    float inv = g_invdeg[node];
    __half2 h = __floats2half2_rn(ax * inv, ay * inv);
    *(unsigned*)(g_a + (size_t)node * F + 2 * lane) = *reinterpret_cast<unsigned*>(&h);
}

// ---------------------------------------------------------------------------
// Fused dual-GEMM + epilogue: out = relu(a@W1) * sigmoid(a@W2).
// HMMA m16n8k16; cols 0..63 = layer1 (nt 0..7), 64..127 = layer2 (nt 8..15):
// the same thread holds both layers for its rows/cols -> register-local fuse.
// ---------------------------------------------------------------------------
__global__ void __launch_bounds__(256) gemm_epi_kernel(float* __restrict__ out) {
    __shared__ __half xs[128][72];
    __shared__ __half ws[128][72];

    int tid = threadIdx.x;
    int row0 = blockIdx.x * 128;

    for (int i = tid; i < 128 * 8; i += 256) {
        int r = i >> 3, ch = i & 7;
        int row = row0 + r;
        uint4 v = make_uint4(0u, 0u, 0u, 0u);
        if (row < N_NODES) v = *(const uint4*)(g_a + (size_t)row * F + ch * 8);
        *(uint4*)&xs[r][ch * 8] = v;
    }
    for (int i = tid; i < 128 * 8; i += 256) {
        int r = i >> 3, ch = i & 7;
        *(uint4*)&ws[r][ch * 8] = *(const uint4*)(g_wt + r * F + ch * 8);
    }
    __syncthreads();

    int warp = tid >> 5, lane = tid & 31;
    int g = lane >> 2, t = lane & 3;
    int wrow = warp * 16;

    float c[16][4];
    #pragma unroll
    for (int nt = 0; nt < 16; nt++)
        #pragma unroll
        for (int j = 0; j < 4; j++) c[nt][j] = 0.0f;

    #pragma unroll
    for (int ks = 0; ks < 4; ks++) {
        int kb = ks * 16;
        unsigned a0 = *(const unsigned*)&xs[wrow + g][kb + 2 * t];
        unsigned a1 = *(const unsigned*)&xs[wrow + g + 8][kb + 2 * t];
        unsigned a2 = *(const unsigned*)&xs[wrow + g][kb + 2 * t + 8];
        unsigned a3 = *(const unsigned*)&xs[wrow + g + 8][kb + 2 * t + 8];
        #pragma unroll
        for (int nt = 0; nt < 16; nt++) {
            unsigned b0 = *(const unsigned*)&ws[nt * 8 + g][kb + 2 * t];
            unsigned b1 = *(const unsigned*)&ws[nt * 8 + g][kb + 2 * t + 8];
            asm volatile(
                "mma.sync.aligned.m16n8k16.row.col.f32.f16.f16.f32 "
                "{%0,%1,%2,%3}, {%4,%5,%6,%7}, {%8,%9}, {%0,%1,%2,%3};"
                : "+f"(c[nt][0]), "+f"(c[nt][1]), "+f"(c[nt][2]), "+f"(c[nt][3])
                : "r"(a0), "r"(a1), "r"(a2), "r"(a3), "r"(b0), "r"(b1));
        }
    }

    int r1 = row0 + wrow + g;
    int r2 = r1 + 8;
    #pragma unroll
    for (int nt = 0; nt < 8; nt++) {
        int col = nt * 8 + 2 * t;
        if (r1 < N_NODES) {
            float2 o;
            o.x = fmaxf(c[nt][0], 0.0f) * (1.0f / (1.0f + expf(-c[nt + 8][0])));
            o.y = fmaxf(c[nt][1], 0.0f) * (1.0f / (1.0f + expf(-c[nt + 8][1])));
            *(float2*)(out + (size_t)r1 * F + col) = o;
        }
        if (r2 < N_NODES) {
            float2 o;
            o.x = fmaxf(c[nt][2], 0.0f) * (1.0f / (1.0f + expf(-c[nt + 8][2])));
            o.y = fmaxf(c[nt][3], 0.0f) * (1.0f / (1.0f + expf(-c[nt + 8][3])));
            *(float2*)(out + (size_t)r2 * F + col) = o;
        }
    }
}

// ---------------------------------------------------------------------------
extern "C" void kernel_launch(void* const* d_in, const int* in_sizes, int n_in,
                              void* d_out, int out_size) {
    const float* x  = (const float*)d_in[0];
    const int*   ei = (const int*)d_in[1];   // int32 (JAX x64 disabled)
    const float* W1 = (const float*)d_in[2];
    const float* W2 = (const float*)d_in[3];
    float* out = (float*)d_out;

    int E  = in_sizes[1] / 2;
    int T4 = (E + 3) / 4;

    prep_kernel<<<(N_NODES * F / 4 + 255) / 256, 256>>>(x, W1, W2);
    scatter_kernel<<<(T4 + 255) / 256, 256>>>(ei, E);
    dinv_kernel<<<(N_NODES + 255) / 256, 256>>>();
    aggx_kernel<<<(N_NODES * 32 + 255) / 256, 256>>>();      // one warp per node
    gemm_epi_kernel<<<(N_NODES + 127) / 128, 256>>>(out);
}

// round 11
// speedup vs baseline: 1.4631x; 1.0513x over previous
#include <cuda_runtime.h>
#include <cuda_fp16.h>

#define N_NODES 50000
#define F 64
#define HDIM 128          // output cols of the dual GEMM (64 + 64)
#define BSTRIDE 128       // bucket region per node (4 reps x 32 cap)
#define BCAP 32
#define NREP 4

// Scratch: __device__ globals (allocation-free, graph-capturable).
// Invariant: g_cursor all-zero at kernel_launch entry (zero at module load;
// aggx_kernel re-zeroes after reading, every run).
__device__ __align__(16) __half g_xh[(size_t)N_NODES * F];   // x in fp16
__device__ __align__(16) __half g_a[(size_t)N_NODES * F];    // aggregated features fp16
__device__ __align__(16) __half g_wt[HDIM * F];              // Wt[c][k] fp16 (n-major)
__device__ float g_dinv[N_NODES];
__device__ float g_invdeg[N_NODES];
__device__ __align__(16) int g_cursor[NREP * N_NODES];       // per (node, rep)
__device__ int g_srcsorted[(size_t)N_NODES * BSTRIDE];       // bucketed src ids

// ---------------------------------------------------------------------------
// Fused: blocks [0, nScatter) bucket-scatter edges; blocks [nScatter, ...)
// convert x -> fp16 and W -> fp16 n-major. Both partitions are resource-light
// (no smem, ~32 regs) so occupancy stays high, and prep's bandwidth hides
// under scatter's L2-latency-bound profile.
// ---------------------------------------------------------------------------
__global__ void __launch_bounds__(256) scatter_prep_kernel(
    const int* __restrict__ ei, int E, int nScatter,
    const float* __restrict__ x,
    const float* __restrict__ W1,
    const float* __restrict__ W2) {

    if ((int)blockIdx.x < nScatter) {
        // ----------------- scatter partition (R7-identical logic) ---------
        int t = blockIdx.x * 256 + threadIdx.x;
        int rep = t & (NREP - 1);
        int base = t * 4;
        if (base + 4 <= E) {
            int4 s = *(const int4*)(ei + base);
            int4 d = *(const int4*)(ei + E + base);
            int p0 = atomicAdd(&g_cursor[d.x * NREP + rep], 1);
            int p1 = atomicAdd(&g_cursor[d.y * NREP + rep], 1);
            int p2 = atomicAdd(&g_cursor[d.z * NREP + rep], 1);
            int p3 = atomicAdd(&g_cursor[d.w * NREP + rep], 1);
            g_srcsorted[(size_t)d.x * BSTRIDE + rep * BCAP + p0] = s.x;
            g_srcsorted[(size_t)d.y * BSTRIDE + rep * BCAP + p1] = s.y;
            g_srcsorted[(size_t)d.z * BSTRIDE + rep * BCAP + p2] = s.z;
            g_srcsorted[(size_t)d.w * BSTRIDE + rep * BCAP + p3] = s.w;
        } else {
            for (int e = base; e < E; e++) {
                int d = ei[E + e];
                int pos = atomicAdd(&g_cursor[d * NREP + rep], 1);
                g_srcsorted[(size_t)d * BSTRIDE + rep * BCAP + pos] = ei[e];
            }
        }
        return;
    }

    // ----------------- prep partition ------------------------------------
    int p = (blockIdx.x - nScatter) * 256 + threadIdx.x;
    if (p < N_NODES * F / 4) {
        float4 v = *(const float4*)(x + (size_t)p * 4);
        __half2 h0 = __floats2half2_rn(v.x, v.y);
        __half2 h1 = __floats2half2_rn(v.z, v.w);
        uint2 o = make_uint2(*reinterpret_cast<unsigned*>(&h0),
                             *reinterpret_cast<unsigned*>(&h1));
        *(uint2*)(g_xh + (size_t)p * 4) = o;
    }
    if (p < HDIM * F) {
        int c = p >> 6, k = p & 63;
        float v = (c < 64) ? W1[k * 64 + c] : W2[k * 64 + (c - 64)];
        g_wt[c * F + k] = __float2half_rn(v);
    }
}

// ---------------------------------------------------------------------------
// deg = sum of 4 cursors + 1 (self loop) -> dinv, invdeg.
// ---------------------------------------------------------------------------
__global__ void __launch_bounds__(256) dinv_kernel() {
    int i = blockIdx.x * blockDim.x + threadIdx.x;
    if (i < N_NODES) {
        int4 c = *(const int4*)(g_cursor + i * NREP);
        float dg = (float)(c.x + c.y + c.z + c.w + 1);
        g_invdeg[i] = 1.0f / dg;
        g_dinv[i]   = rsqrtf(dg);
    }
}

// ---------------------------------------------------------------------------
// Aggregate x: a[dst] = (sum norm*xh[src] + dinv^2*xh[dst]) / deg.
// TWO nodes per warp: lanes 0-15 -> node 2w, lanes 16-31 -> node 2w+1.
// Lane owns 4 cols (uint2 = 8B; 16 lanes x 8B = one 128B row per half-warp),
// so each warp-instruction advances two edges. Both halves iterate to the
// warp-max subchunk count; padded entries have nrm=0 (harmless).
// Re-zeroes the two nodes' cursors at the end (restores entry invariant).
// ---------------------------------------------------------------------------
__global__ void __launch_bounds__(256) aggx_kernel() {
    int w    = (blockIdx.x * blockDim.x + threadIdx.x) >> 5;
    int lane = threadIdx.x & 31;
    int half = lane >> 4;          // 0 or 1
    int hl   = lane & 15;          // lane within half
    int node = w * 2 + half;
    if (node >= N_NODES) return;   // N_NODES even: whole warp exits together

    float di = g_dinv[node];
    int4 cc = *(const int4*)(g_cursor + node * NREP);
    if (hl == 0)
        *(int4*)(g_cursor + node * NREP) = make_int4(0, 0, 0, 0);
    int cnt_arr[4] = {cc.x, cc.y, cc.z, cc.w};

    // self-loop term: di*di * xh[node], lane's 4 cols
    float ax, ay, az, aw;
    {
        uint2 u = *((const uint2*)(g_xh + (size_t)node * F) + hl);
        float2 f0 = __half22float2(*reinterpret_cast<__half2*>(&u.x));
        float2 f1 = __half22float2(*reinterpret_cast<__half2*>(&u.y));
        float self = di * di;
        ax = self * f0.x; ay = self * f0.y; az = self * f1.x; aw = self * f1.y;
    }

    #pragma unroll
    for (int rep = 0; rep < NREP; rep++) {
        int cnt = cnt_arr[rep];
        const int* src = g_srcsorted + (size_t)node * BSTRIDE + rep * BCAP;

        // preload bucket entries: lo = entries 0..15, hi = 16..31 (per half)
        int   s_lo = node; float n_lo = 0.0f;
        if (hl < cnt)      { s_lo = src[hl];      n_lo = di * g_dinv[s_lo]; }
        int   s_hi = node; float n_hi = 0.0f;
        if (hl + 16 < cnt) { s_hi = src[hl + 16]; n_hi = di * g_dinv[s_hi]; }

        int nsub = (cnt + 7) >> 3;
        int nsub_other = __shfl_xor_sync(0xffffffffu, nsub, 16);
        int nsub_max = max(nsub, nsub_other);

        int selbase = half << 4;   // shfl source base for my half
        for (int sub = 0; sub < nsub_max; sub++) {
            int   sv = (sub < 2) ? s_lo : s_hi;
            float nv = (sub < 2) ? n_lo : n_hi;
            int   off = selbase + (sub & 1) * 8;
            #pragma unroll
            for (int u = 0; u < 8; u++) {
                int   ss = __shfl_sync(0xffffffffu, sv, off + u);
                float nn = __shfl_sync(0xffffffffu, nv, off + u);
                uint2 v = *((const uint2*)(g_xh + (size_t)ss * F) + hl);
                float2 f0 = __half22float2(*reinterpret_cast<__half2*>(&v.x));
                float2 f1 = __half22float2(*reinterpret_cast<__half2*>(&v.y));
                ax = fmaf(nn, f0.x, ax);
                ay = fmaf(nn, f0.y, ay);
                az = fmaf(nn, f1.x, az);
                aw = fmaf(nn, f1.y, aw);
            }
        }
    }

    float inv = g_invdeg[node];
    __half2 h0 = __floats2half2_rn(ax * inv, ay * inv);
    __half2 h1 = __floats2half2_rn(az * inv, aw * inv);
    uint2 o = make_uint2(*reinterpret_cast<unsigned*>(&h0),
                         *reinterpret_cast<unsigned*>(&h1));
    *((uint2*)(g_a + (size_t)node * F) + hl) = o;
}

// ---------------------------------------------------------------------------
// Fused dual-GEMM + epilogue: out = relu(a@W1) * sigmoid(a@W2).
// HMMA m16n8k16; cols 0..63 = layer1 (nt 0..7), 64..127 = layer2 (nt 8..15):
// the same thread holds both layers for its rows/cols -> register-local fuse.
// ---------------------------------------------------------------------------
__global__ void __launch_bounds__(256) gemm_epi_kernel(float* __restrict__ out) {
    __shared__ __half xs[128][72];
    __shared__ __half ws[128][72];

    int tid = threadIdx.x;
    int row0 = blockIdx.x * 128;

    for (int i = tid; i < 128 * 8; i += 256) {
        int r = i >> 3, ch = i & 7;
        int row = row0 + r;
        uint4 v = make_uint4(0u, 0u, 0u, 0u);
        if (row < N_NODES) v = *(const uint4*)(g_a + (size_t)row * F + ch * 8);
        *(uint4*)&xs[r][ch * 8] = v;
    }
    for (int i = tid; i < 128 * 8; i += 256) {
        int r = i >> 3, ch = i & 7;
        *(uint4*)&ws[r][ch * 8] = *(const uint4*)(g_wt + r * F + ch * 8);
    }
    __syncthreads();

    int warp = tid >> 5, lane = tid & 31;
    int g = lane >> 2, t = lane & 3;
    int wrow = warp * 16;

    float c[16][4];
    #pragma unroll
    for (int nt = 0; nt < 16; nt++)
        #pragma unroll
        for (int j = 0; j < 4; j++) c[nt][j] = 0.0f;

    #pragma unroll
    for (int ks = 0; ks < 4; ks++) {
        int kb = ks * 16;
        unsigned a0 = *(const unsigned*)&xs[wrow + g][kb + 2 * t];
        unsigned a1 = *(const unsigned*)&xs[wrow + g + 8][kb + 2 * t];
        unsigned a2 = *(const unsigned*)&xs[wrow + g][kb + 2 * t + 8];
        unsigned a3 = *(const unsigned*)&xs[wrow + g + 8][kb + 2 * t + 8];
        #pragma unroll
        for (int nt = 0; nt < 16; nt++) {
            unsigned b0 = *(const unsigned*)&ws[nt * 8 + g][kb + 2 * t];
            unsigned b1 = *(const unsigned*)&ws[nt * 8 + g][kb + 2 * t + 8];
            asm volatile(
                "mma.sync.aligned.m16n8k16.row.col.f32.f16.f16.f32 "
                "{%0,%1,%2,%3}, {%4,%5,%6,%7}, {%8,%9}, {%0,%1,%2,%3};"
                : "+f"(c[nt][0]), "+f"(c[nt][1]), "+f"(c[nt][2]), "+f"(c[nt][3])
                : "r"(a0), "r"(a1), "r"(a2), "r"(a3), "r"(b0), "r"(b1));
        }
    }

    int r1 = row0 + wrow + g;
    int r2 = r1 + 8;
    #pragma unroll
    for (int nt = 0; nt < 8; nt++) {
        int col = nt * 8 + 2 * t;
        if (r1 < N_NODES) {
            float2 o;
            o.x = fmaxf(c[nt][0], 0.0f) * (1.0f / (1.0f + expf(-c[nt + 8][0])));
            o.y = fmaxf(c[nt][1], 0.0f) * (1.0f / (1.0f + expf(-c[nt + 8][1])));
            *(float2*)(out + (size_t)r1 * F + col) = o;
        }
        if (r2 < N_NODES) {
            float2 o;
            o.x = fmaxf(c[nt][2], 0.0f) * (1.0f / (1.0f + expf(-c[nt + 8][2])));
            o.y = fmaxf(c[nt][3], 0.0f) * (1.0f / (1.0f + expf(-c[nt + 8][3])));
            *(float2*)(out + (size_t)r2 * F + col) = o;
        }
    }
}

// ---------------------------------------------------------------------------
extern "C" void kernel_launch(void* const* d_in, const int* in_sizes, int n_in,
                              void* d_out, int out_size) {
    const float* x  = (const float*)d_in[0];
    const int*   ei = (const int*)d_in[1];   // int32 (JAX x64 disabled)
    const float* W1 = (const float*)d_in[2];
    const float* W2 = (const float*)d_in[3];
    float* out = (float*)d_out;

    int E  = in_sizes[1] / 2;
    int T4 = (E + 3) / 4;
    int S  = (T4 + 255) / 256;                       // scatter blocks (first)
    int P  = (N_NODES * F / 4 + 255) / 256;          // prep blocks

    scatter_prep_kernel<<<S + P, 256>>>(ei, E, S, x, W1, W2);
    dinv_kernel<<<(N_NODES + 255) / 256, 256>>>();
    aggx_kernel<<<(N_NODES / 2 * 32 + 255) / 256, 256>>>();  // 2 nodes per warp
    gemm_epi_kernel<<<(N_NODES + 127) / 128, 256>>>(out);
}